// round 12
// baseline (speedup 1.0000x reference)
#include <cuda_runtime.h>
#include <cuda_fp16.h>
#include <math.h>
#include <stdint.h>

#define BDIM 384
#define HEADS 8
#define HD 48
#define NSEQ 2048
#define NB 4
#define MROWS (NB*NSEQ)      /* 8192 */
#define MLPH 1536
#define QKVN (3*BDIM)        /* 1152 */
#define SCALE2F (0.14433756729740643f * 1.4426950408889634f)  /* 48^-0.5 * log2e */

/* ------------ scratch (device globals; no allocation allowed) ------------ */
__device__ __half g_h16 [MROWS*BDIM];
__device__ __half g_q16 [MROWS*BDIM];
__device__ __half g_k16 [MROWS*BDIM];
__device__ __half g_v16t[MROWS*BDIM];          /* V^T: [bh][d][n] */
__device__ __half g_att16[MROWS*BDIM];
__device__ __half g_hid16[MROWS*MLPH];
__device__ __half g_wqkvT[QKVN*BDIM];
__device__ __half g_woT  [BDIM*BDIM];
__device__ __half g_mw1T [MLPH*BDIM];
__device__ __half g_mw2T [BDIM*MLPH];
__device__ float  g_pe[MROWS*HD];
__device__ float  g_x1[MROWS*BDIM];
__device__ int    g_mask[MROWS];
__device__ float  g_mb [MROWS];
__device__ float  g_bqkv[QKVN];

__device__ __forceinline__ float gelu_exact(float x) {
    return 0.5f * x * (1.0f + erff(x * 0.70710678118654752f));
}
__device__ __forceinline__ float ex2(float x) {
    float y; asm("ex2.approx.f32 %0, %1;" : "=f"(y) : "f"(x)); return y;
}
__device__ __forceinline__ uint32_t h2ex2(uint32_t x) {
    uint32_t y; asm("ex2.approx.f16x2 %0, %1;" : "=r"(y) : "r"(x)); return y;
}

/* m16n8k16 fp16 mma, fp32 accumulate. regs are packed half2. */
__device__ __forceinline__ void mma16(float* c,
                                      uint32_t a0, uint32_t a1, uint32_t a2, uint32_t a3,
                                      uint32_t b0, uint32_t b1) {
    asm volatile(
      "mma.sync.aligned.m16n8k16.row.col.f32.f16.f16.f32 "
      "{%0,%1,%2,%3},{%4,%5,%6,%7},{%8,%9},{%0,%1,%2,%3};"
      : "+f"(c[0]), "+f"(c[1]), "+f"(c[2]), "+f"(c[3])
      : "r"(a0), "r"(a1), "r"(a2), "r"(a3), "r"(b0), "r"(b1));
}

__device__ __forceinline__ void ldsm4(uint32_t& r0, uint32_t& r1,
                                      uint32_t& r2, uint32_t& r3, uint32_t a) {
    asm volatile("ldmatrix.sync.aligned.m8n8.x4.shared.b16 {%0,%1,%2,%3}, [%4];"
                 : "=r"(r0), "=r"(r1), "=r"(r2), "=r"(r3) : "r"(a));
}
__device__ __forceinline__ void ldsm2(uint32_t& r0, uint32_t& r1, uint32_t a) {
    asm volatile("ldmatrix.sync.aligned.m8n8.x2.shared.b16 {%0,%1}, [%2];"
                 : "=r"(r0), "=r"(r1) : "r"(a));
}
__device__ __forceinline__ uint32_t s2u(const void* p) {
    return (uint32_t)__cvta_generic_to_shared(p);
}
__device__ __forceinline__ void cpa16(void* dst, const void* src) {
    uint32_t d = s2u(dst);
    asm volatile("cp.async.ca.shared.global [%0], [%1], 16;" :: "r"(d), "l"(src));
}
__device__ __forceinline__ void cpa4(void* dst, const void* src) {
    uint32_t d = s2u(dst);
    asm volatile("cp.async.ca.shared.global [%0], [%1], 4;" :: "r"(d), "l"(src));
}
#define CP_COMMIT() asm volatile("cp.async.commit_group;")
template<int N> __device__ __forceinline__ void cp_wait() {
    asm volatile("cp.async.wait_group %0;" :: "n"(N));
}
__device__ __forceinline__ uint32_t h2pack(float a, float b) {
    __half2 h = __floats2half2_rn(a, b);
    return *(uint32_t*)&h;
}

/* ======================= fused prep kernel bodies ======================= */

__device__ __forceinline__ void ln_body(const float* __restrict__ X,
                                        const float* __restrict__ g,
                                        const float* __restrict__ be,
                                        __half* __restrict__ Y, int blk) {
    int tid = threadIdx.x, lane = tid & 31, w = tid >> 5;
    int row = blk*8 + w;
    const float* x = X + (size_t)row * BDIM;
    __half*      y = Y + (size_t)row * BDIM;
    float4 v[3];
    float s = 0.f, sq = 0.f;
    #pragma unroll
    for (int i = 0; i < 3; i++) {
        v[i] = *(const float4*)(x + lane*4 + i*128);
        s  += v[i].x + v[i].y + v[i].z + v[i].w;
        sq += v[i].x*v[i].x + v[i].y*v[i].y + v[i].z*v[i].z + v[i].w*v[i].w;
    }
    #pragma unroll
    for (int o = 16; o; o >>= 1) {
        s  += __shfl_xor_sync(0xffffffffu, s,  o);
        sq += __shfl_xor_sync(0xffffffffu, sq, o);
    }
    float mean = s * (1.0f / BDIM);
    float var  = sq * (1.0f / BDIM) - mean * mean;
    float rstd = rsqrtf(var + 1e-5f);
    #pragma unroll
    for (int i = 0; i < 3; i++) {
        int c = lane*4 + i*128;
        float4 gg = *(const float4*)(g + c);
        float4 bb = *(const float4*)(be + c);
        uint2 st;
        st.x = h2pack((v[i].x - mean)*rstd*gg.x + bb.x,
                      (v[i].y - mean)*rstd*gg.y + bb.y);
        st.y = h2pack((v[i].z - mean)*rstd*gg.z + bb.z,
                      (v[i].w - mean)*rstd*gg.w + bb.w);
        *(uint2*)(y + c) = st;
    }
}

__device__ __forceinline__ void pe_body(float* sh,
                                        const float* __restrict__ pos,
                                        const float* __restrict__ pw1,
                                        const float* __restrict__ pb1,
                                        const float* __restrict__ pw2,
                                        const float* __restrict__ pb2,
                                        float* __restrict__ pe, int blk) {
    float* w2s = sh;            /* 2304 */
    float* w1s = sh + 2304;     /* 144 */
    float* b1s = sh + 2448;     /* 48 */
    float* b2s = sh + 2496;     /* 48 */
    int tid = threadIdx.x, lane = tid & 31, w = tid >> 5;
    for (int i = tid; i < HD*HD; i += 256) w2s[i] = pw2[i];
    if (tid < 3*HD) w1s[tid] = pw1[tid];
    else if (tid < 4*HD) b1s[tid - 3*HD] = pb1[tid - 3*HD];
    else if (tid < 5*HD) b2s[tid - 4*HD] = pb2[tid - 4*HD];
    __syncthreads();
    int row = blk*8 + w;
    float p0 = pos[row*3], p1 = pos[row*3+1], p2 = pos[row*3+2];
    float h0, h1 = 0.f;
    {
        int k = lane;
        h0 = gelu_exact(p0*w1s[k] + p1*w1s[HD+k] + p2*w1s[2*HD+k] + b1s[k]);
    }
    if (lane < 16) {
        int k = 32 + lane;
        h1 = gelu_exact(p0*w1s[k] + p1*w1s[HD+k] + p2*w1s[2*HD+k] + b1s[k]);
    }
    float acc0 = b2s[lane];
    float acc1 = (lane < 16) ? b2s[32 + lane] : 0.f;
    #pragma unroll 8
    for (int k = 0; k < HD; k++) {
        float hk = (k < 32) ? __shfl_sync(0xffffffffu, h0, k)
                            : __shfl_sync(0xffffffffu, h1, k - 32);
        acc0 += hk * w2s[k*HD + lane];
        if (lane < 16) acc1 += hk * w2s[k*HD + 32 + lane];
    }
    pe[(size_t)row*HD + lane] = acc0;
    if (lane < 16) pe[(size_t)row*HD + 32 + lane] = acc1;
}

__device__ __forceinline__ void transpose_body(float* sh,
                                               const float* __restrict__ Wq,
                                               const float* __restrict__ Wk,
                                               const float* __restrict__ Wv,
                                               const float* __restrict__ Wo,
                                               const float* __restrict__ mw1,
                                               const float* __restrict__ mw2,
                                               __half* __restrict__ wqkvT,
                                               __half* __restrict__ woT,
                                               __half* __restrict__ mw1T,
                                               __half* __restrict__ mw2T, int tIdx) {
    const float* W; __half* Wt; int K, N;
    if (tIdx < 432) {
        int seg = tIdx / 144;
        W  = (seg == 0) ? Wq : (seg == 1) ? Wk : Wv;
        Wt = wqkvT + (size_t)seg * BDIM * BDIM;
        K = BDIM; N = BDIM; tIdx -= seg * 144;
    } else if (tIdx < 576) { W = Wo;  Wt = woT;  K = BDIM; N = BDIM; tIdx -= 432; }
    else if   (tIdx < 1152) { W = mw1; Wt = mw1T; K = BDIM; N = MLPH; tIdx -= 576; }
    else                    { W = mw2; Wt = mw2T; K = MLPH; N = BDIM; tIdx -= 1152; }
    int nt = N / 32;
    int n0 = (tIdx % nt) * 32, k0 = (tIdx / nt) * 32;
    int tx = threadIdx.x & 31, ty = threadIdx.x >> 5;  /* 32 x 8 */
    #pragma unroll
    for (int i = 0; i < 32; i += 8)
        sh[(ty+i)*33 + tx] = W[(size_t)(k0+ty+i)*N + n0+tx];
    __syncthreads();
    #pragma unroll
    for (int i = 0; i < 32; i += 8)
        Wt[(size_t)(n0+ty+i)*K + k0+tx] = __float2half_rn(sh[tx*33 + ty+i]);
}

__device__ __forceinline__ void mask_body(float* sh, const void* __restrict__ mptr,
                                          int n, int* __restrict__ out,
                                          float* __restrict__ fb) {
    int* ish = (int*)sh;
    const unsigned char* b = (const unsigned char*)mptr;
    if (threadIdx.x == 0) { ish[0] = 0; ish[1] = 0; }
    __syncthreads();
    int lf = 0, ln4 = 0;
    for (int i = threadIdx.x; i < n; i += 256) {
        unsigned char c = b[i];
        if (c == 0x3Fu && (i & 3) == 3) lf = 1;
        if (c != 0u   && (i & 3) != 0) ln4 = 1;
    }
    if (lf)  atomicOr(&ish[0], 1);
    if (ln4) atomicOr(&ish[1], 1);
    __syncthreads();
    int mode = ish[0] ? 2 : (ish[1] ? 0 : 1);
    for (int i = threadIdx.x; i < n; i += 256) {
        int v;
        if      (mode == 0) v = (b[i] != 0);
        else if (mode == 1) v = (((const int*)mptr)[i]   != 0);
        else                v = (((const float*)mptr)[i] != 0.0f);
        out[i] = v;
        fb[i]  = v ? 0.0f : -1e30f;
    }
}

__global__ __launch_bounds__(256)
void prep_kernel(const float* __restrict__ x,
                 const float* __restrict__ g1, const float* __restrict__ be1,
                 __half* __restrict__ h16,
                 const float* __restrict__ pos,
                 const float* __restrict__ pw1, const float* __restrict__ pb1,
                 const float* __restrict__ pw2, const float* __restrict__ pb2,
                 float* __restrict__ pe,
                 const float* __restrict__ Wq, const float* __restrict__ Wk,
                 const float* __restrict__ Wv, const float* __restrict__ Wo,
                 const float* __restrict__ mw1, const float* __restrict__ mw2,
                 __half* __restrict__ wqkvT, __half* __restrict__ woT,
                 __half* __restrict__ mw1T, __half* __restrict__ mw2T,
                 const void* __restrict__ mask, int* __restrict__ msk,
                 float* __restrict__ mbf,
                 const float* __restrict__ bq, const float* __restrict__ bk,
                 const float* __restrict__ bv, float* __restrict__ bqkv) {
    __shared__ float sh[2544];
    int bid = blockIdx.x;
    if (bid < 1024) {
        ln_body(x, g1, be1, h16, bid);
    } else if (bid < 2048) {
        pe_body(sh, pos, pw1, pb1, pw2, pb2, pe, bid - 1024);
    } else if (bid < 3776) {
        transpose_body(sh, Wq, Wk, Wv, Wo, mw1, mw2,
                       wqkvT, woT, mw1T, mw2T, bid - 2048);
    } else if (bid == 3776) {
        mask_body(sh, mask, MROWS, msk, mbf);
    } else {
        for (int i = threadIdx.x; i < QKVN; i += 256) {
            int sec = i / BDIM, c = i % BDIM;
            bqkv[i] = (sec == 0) ? bq[c] : (sec == 1) ? bk[c] : bv[c];
        }
    }
}

/* standalone LN (for LN2) */
__global__ __launch_bounds__(256)
void ln_kernel(const float* __restrict__ X,
               const float* __restrict__ g,
               const float* __restrict__ be,
               __half* __restrict__ Y) {
    ln_body(X, g, be, Y, blockIdx.x);
}

/* ------------ fp16 GEMM: 128x64x32, 3-stage cp.async, 1 barrier/iter,
   3 blocks/SM (occupancy-optimized).  EPI 1 pre-scales Q by SCALE2F. ------ */
#define GBM 128
#define GBN 64
#define GBK 32
#define APADH 40
#define BPADH 40
#define AST (GBM*APADH)
#define BST (GBN*BPADH)

template<int EPI>
__global__ __launch_bounds__(256, 3)
void gemm_tc(const __half* __restrict__ A, const __half* __restrict__ Bt,
             const float* __restrict__ bias,
             int K, int Nc,
             const float* __restrict__ extra, const int* __restrict__ mask,
             float* __restrict__ Cf, __half* __restrict__ Ch,
             __half* __restrict__ Ck, __half* __restrict__ Cv) {
    __shared__ __half As[3*AST];
    __shared__ __half Bs[3*BST];
    int tid = threadIdx.x, lane = tid & 31, w = tid >> 5;
    int g = lane >> 2, t = lane & 3;
    int wm = w >> 1, wn = w & 1;
    int bm = blockIdx.x * GBM, bn = blockIdx.y * GBN;
    int mlow = (lane >> 3) & 1, mhigh = lane >> 4, rr = lane & 7;

    float acc[2][4][4];
    #pragma unroll
    for (int mi = 0; mi < 2; mi++)
        #pragma unroll
        for (int nj = 0; nj < 4; nj++)
            #pragma unroll
            for (int r = 0; r < 4; r++) acc[mi][nj][r] = 0.f;

    int a_r = tid >> 2, a_c = (tid & 3) * 8;
    int b_r = tid >> 2, b_c = (tid & 3) * 8;

    uint32_t As_u = s2u(As);
    uint32_t Bs_u = s2u(Bs);
    uint32_t aoff0 = ((wm*32 + mlow*8 + rr)*APADH + mhigh*8)*2;
    uint32_t aoff1 = aoff0 + 16*APADH*2;
    uint32_t boff0 = ((wn*32 + mhigh*8 + rr)*BPADH + mlow*8)*2;
    uint32_t boff1 = boff0 + 16*BPADH*2;

    int ntiles = K / GBK;
    #pragma unroll
    for (int p = 0; p < 2; p++) {
        int k0 = p * GBK;
        cpa16(&As[p*AST + a_r*APADH + a_c], A + (size_t)(bm + a_r)*K + k0 + a_c);
        cpa16(&As[p*AST + (a_r+64)*APADH + a_c], A + (size_t)(bm + a_r + 64)*K + k0 + a_c);
        cpa16(&Bs[p*BST + b_r*BPADH + b_c], Bt + (size_t)(bn + b_r)*K + k0 + b_c);
        CP_COMMIT();
    }

    int st = 0;
    for (int kt = 0; kt < ntiles; kt++) {
        cp_wait<1>();
        __syncthreads();
        if (kt + 2 < ntiles) {
            int k0 = (kt + 2) * GBK;
            int sn = st + 2; if (sn >= 3) sn -= 3;
            cpa16(&As[sn*AST + a_r*APADH + a_c], A + (size_t)(bm + a_r)*K + k0 + a_c);
            cpa16(&As[sn*AST + (a_r+64)*APADH + a_c], A + (size_t)(bm + a_r + 64)*K + k0 + a_c);
            cpa16(&Bs[sn*BST + b_r*BPADH + b_c], Bt + (size_t)(bn + b_r)*K + k0 + b_c);
        }
        CP_COMMIT();

        uint32_t asb = As_u + st*(AST*2);
        uint32_t bsb = Bs_u + st*(BST*2);
        #pragma unroll
        for (int ks = 0; ks < 2; ks++) {
            uint32_t kbb = ks*32;
            uint32_t af0[4], af1[4], bb0[4], bb1[4];
            ldsm4(af0[0], af0[1], af0[2], af0[3], asb + aoff0 + kbb);
            ldsm4(af1[0], af1[1], af1[2], af1[3], asb + aoff1 + kbb);
            ldsm4(bb0[0], bb0[1], bb0[2], bb0[3], bsb + boff0 + kbb);
            ldsm4(bb1[0], bb1[1], bb1[2], bb1[3], bsb + boff1 + kbb);
            mma16(acc[0][0], af0[0], af0[1], af0[2], af0[3], bb0[0], bb0[1]);
            mma16(acc[0][1], af0[0], af0[1], af0[2], af0[3], bb0[2], bb0[3]);
            mma16(acc[0][2], af0[0], af0[1], af0[2], af0[3], bb1[0], bb1[1]);
            mma16(acc[0][3], af0[0], af0[1], af0[2], af0[3], bb1[2], bb1[3]);
            mma16(acc[1][0], af1[0], af1[1], af1[2], af1[3], bb0[0], bb0[1]);
            mma16(acc[1][1], af1[0], af1[1], af1[2], af1[3], bb0[2], bb0[3]);
            mma16(acc[1][2], af1[0], af1[1], af1[2], af1[3], bb1[0], bb1[1]);
            mma16(acc[1][3], af1[0], af1[1], af1[2], af1[3], bb1[2], bb1[3]);
        }
        if (++st == 3) st = 0;
    }

    #pragma unroll
    for (int mi = 0; mi < 2; mi++) {
        #pragma unroll
        for (int half = 0; half < 2; half++) {
            int row = bm + wm*32 + mi*16 + g + half*8;
            #pragma unroll
            for (int nj = 0; nj < 4; nj++) {
                int col = bn + wn*32 + nj*8 + 2*t;
                float v0 = acc[mi][nj][half*2+0] + bias[col];
                float v1 = acc[mi][nj][half*2+1] + bias[col+1];
                if (EPI == 1) {
                    int sec = col / BDIM;
                    int c2  = col - sec*BDIM;
                    int d = c2 % HD, hh = c2 / HD;
                    int bb = row >> 11, n = row & (NSEQ-1);
                    if (sec == 2) {
                        __half* p = Cv + ((size_t)((bb*HEADS + hh)*HD + d))*NSEQ + n;
                        p[0]    = __float2half_rn(v0);
                        p[NSEQ] = __float2half_rn(v1);
                    } else if (sec == 1) {
                        v0 += extra[(size_t)row*HD + d];
                        v1 += extra[(size_t)row*HD + d + 1];
                        __half* p = Ck + (((size_t)(bb*HEADS + hh))*NSEQ + n)*HD + d;
                        *(uint32_t*)p = h2pack(v0, v1);
                    } else {
                        /* Q pre-scaled for exp2-domain softmax */
                        v0 *= SCALE2F; v1 *= SCALE2F;
                        __half* p = Ch + (((size_t)(bb*HEADS + hh))*NSEQ + n)*HD + d;
                        *(uint32_t*)p = h2pack(v0, v1);
                    }
                } else if (EPI == 2) {
                    float m = (float)mask[row];
                    v0 = v0*m + extra[(size_t)row*Nc + col];
                    v1 = v1*m + extra[(size_t)row*Nc + col + 1];
                    float* p = Cf + (size_t)row*Nc + col;
                    p[0] = v0; p[1] = v1;
                } else if (EPI == 3) {
                    *(uint32_t*)(Ch + (size_t)row*Nc + col) =
                        h2pack(gelu_exact(v0), gelu_exact(v1));
                } else {
                    float m = (float)mask[row];
                    v0 = (v0 + extra[(size_t)row*Nc + col])*m;
                    v1 = (v1 + extra[(size_t)row*Nc + col + 1])*m;
                    float* p = Cf + (size_t)row*Nc + col;
                    p[0] = v0; p[1] = v1;
                }
            }
        }
    }
}

/* ------- flash attention: register-direct P, Q pre-scaled (no FMUL) ------- */
#define KPADH 56
#define VTPADH 72
#define BQ 128
#define NT (NSEQ/64)
#define KST (64*KPADH)
#define VST (56*VTPADH)                              /* rows 48..55 = ones/zeros */
#define ATT_H_KS 0
#define ATT_H_VT (3*KST)                             /* 10752 */
#define ATT_H_QS (ATT_H_VT + 3*VST)                  /* 22848 */
#define ATT_H_END (ATT_H_QS + 128*KPADH)             /* 30016 halves */
#define ATT_MB_OFF ATT_H_END
#define ATT_SMEM (ATT_H_END*2 + 3*64*4)              /* 60800 B */

__global__ __launch_bounds__(256, 2)
void attn_tc(const __half* __restrict__ Q, const __half* __restrict__ Kb,
             const __half* __restrict__ Vt, const float* __restrict__ mb,
             __half* __restrict__ O) {
    extern __shared__ __half smh[];
    __half* Ks  = smh + ATT_H_KS;
    __half* Vts = smh + ATT_H_VT;
    __half* Qs  = smh + ATT_H_QS;
    float*  MBs = (float*)(smh + ATT_MB_OFF);

    int bh = blockIdx.y, b = bh >> 3, h = bh & 7;
    int q0 = blockIdx.x * BQ;
    int tid = threadIdx.x, lane = tid & 31, w = tid >> 5;
    int g = lane >> 2, t = lane & 3;
    int mlow = (lane >> 3) & 1, mhigh = lane >> 4, rr = lane & 7;
    const __half* qp = Q  + (size_t)bh * NSEQ * HD;
    const __half* kp = Kb + (size_t)bh * NSEQ * HD;
    const __half* vp = Vt + (size_t)bh * NSEQ * HD;   /* [d][n] */
    const float* mbp = mb + b * NSEQ;

    uint32_t Ks_u = s2u(Ks), Vt_u = s2u(Vts), Qs_u = s2u(Qs);
    uint32_t koff = ((mhigh*8 + rr)*KPADH + mlow*8)*2;
    uint32_t voff = ((mhigh*8 + rr)*VTPADH + mlow*8)*2;
    uint32_t loff = ((48 + rr)*VTPADH + mlow*8)*2;    /* ones-row ldsm.x2 */
    uint32_t qoff = Qs_u + ((w*16 + mlow*8 + rr)*KPADH + mhigh*8)*2;

    /* prologue FIRST: issue K/V/MB tiles 0 and 1 (overlaps Q staging) */
    #pragma unroll
    for (int p = 0; p < 2; p++) {
        int k0 = p * 64;
        #pragma unroll
        for (int i = 0; i < 2; i++) {
            int idx = tid + i*256;
            if (idx < 384) {
                int r = idx / 6, c = (idx % 6) * 8;
                cpa16(Ks + p*KST + r*KPADH + c, kp + (size_t)(k0 + r)*HD + c);
                int rv = idx >> 3, cv = (idx & 7) * 8;
                cpa16(Vts + p*VST + rv*VTPADH + cv, vp + (size_t)rv*NSEQ + k0 + cv);
            }
        }
        if (tid < 64) cpa4(MBs + p*64 + tid, mbp + k0 + tid);
        CP_COMMIT();
    }

    /* init ones/zeros rows 48..55 of V^T stages (never touched by cp.async) */
    {
        const __half one = __float2half(1.0f), zero = __float2half(0.0f);
        for (int idx = tid; idx < 3*8*64; idx += 256) {
            int stg = idx / 512, rem = idx - stg*512;
            int rw = 48 + rem / 64, cc = rem % 64;
            Vts[stg*VST + rw*VTPADH + cc] = (rw == 48) ? one : zero;
        }
    }

    /* stage Q ([128][56] halves), extract fragments via ldmatrix */
    #pragma unroll
    for (int i = 0; i < 3; i++) {
        int idx = tid + i*256;
        int r = idx / 6, c = (idx % 6) * 8;
        *(uint4*)(Qs + r*KPADH + c) = *(const uint4*)(qp + (size_t)(q0 + r)*HD + c);
    }
    __syncthreads();
    uint32_t qf[3][4];
    #pragma unroll
    for (int ks = 0; ks < 3; ks++)
        ldsm4(qf[ks][0], qf[ks][1], qf[ks][2], qf[ks][3], qoff + ks*32);

    float o[6][4];
    #pragma unroll
    for (int nj = 0; nj < 6; nj++)
        #pragma unroll
        for (int r = 0; r < 4; r++) o[nj][r] = 0.f;
    float l4[4] = {0.f, 0.f, 0.f, 0.f};
    float mA = -INFINITY, mB = -INFINITY;

    int st = 0;
    for (int kt = 0; kt < NT; kt++) {
        cp_wait<1>();
        __syncthreads();
        if (kt + 2 < NT) {
            int k0 = (kt + 2) * 64;
            int sn = st + 2; if (sn >= 3) sn -= 3;
            #pragma unroll
            for (int i = 0; i < 2; i++) {
                int idx = tid + i*256;
                if (idx < 384) {
                    int r = idx / 6, c = (idx % 6) * 8;
                    cpa16(Ks + sn*KST + r*KPADH + c, kp + (size_t)(k0 + r)*HD + c);
                    int rv = idx >> 3, cv = (idx & 7) * 8;
                    cpa16(Vts + sn*VST + rv*VTPADH + cv, vp + (size_t)rv*NSEQ + k0 + cv);
                }
            }
            if (tid < 64) cpa4(MBs + sn*64 + tid, mbp + k0 + tid);
        }
        CP_COMMIT();

        uint32_t Kst_u = Ks_u + st*KST*2;
        uint32_t Vst_u = Vt_u + st*VST*2;
        const float* MBst = MBs + st*64;

        /* S = Q K^T : warp tile 16x64 (already exp2-domain; Q pre-scaled) */
        float s[8][4];
        #pragma unroll
        for (int nj = 0; nj < 8; nj++)
            #pragma unroll
            for (int r = 0; r < 4; r++) s[nj][r] = 0.f;
        #pragma unroll
        for (int ks = 0; ks < 3; ks++) {
            uint32_t kbb = ks*32;
            #pragma unroll
            for (int njp = 0; njp < 4; njp++) {
                uint32_t b0, b1, b2, b3;
                ldsm4(b0, b1, b2, b3, Kst_u + koff + njp*16*KPADH*2 + kbb);
                mma16(s[2*njp],   qf[ks][0], qf[ks][1], qf[ks][2], qf[ks][3], b0, b1);
                mma16(s[2*njp+1], qf[ks][0], qf[ks][1], qf[ks][2], qf[ks][3], b2, b3);
            }
        }

        /* + mask bias (pure FADD), row max */
        float mxA = -INFINITY, mxB = -INFINITY;
        #pragma unroll
        for (int nj = 0; nj < 8; nj++) {
            float2 mbv = *(const float2*)(MBst + nj*8 + 2*t);
            s[nj][0] += mbv.x;
            s[nj][1] += mbv.y;
            s[nj][2] += mbv.x;
            s[nj][3] += mbv.y;
            mxA = fmaxf(mxA, fmaxf(s[nj][0], s[nj][1]));
            mxB = fmaxf(mxB, fmaxf(s[nj][2], s[nj][3]));
        }
        mxA = fmaxf(mxA, __shfl_xor_sync(0xffffffffu, mxA, 1));
        mxA = fmaxf(mxA, __shfl_xor_sync(0xffffffffu, mxA, 2));
        mxB = fmaxf(mxB, __shfl_xor_sync(0xffffffffu, mxB, 1));
        mxB = fmaxf(mxB, __shfl_xor_sync(0xffffffffu, mxB, 2));

        float mAn = fmaxf(mA, mxA), fA = ex2(mA - mAn);
        float mBn = fmaxf(mB, mxB), fB = ex2(mB - mBn);
        mA = mAn; mB = mBn;

        /* rescale output + l accumulators */
        #pragma unroll
        for (int nj = 0; nj < 6; nj++) {
            o[nj][0] *= fA; o[nj][1] *= fA;
            o[nj][2] *= fB; o[nj][3] *= fB;
        }
        l4[0] *= fA; l4[2] *= fB;

        /* P = exp2(S-m) REGISTER-DIRECT into PV mma (S C-frag == PV A-frag) */
        #pragma unroll
        for (int ks = 0; ks < 4; ks++) {
            uint32_t kbb = ks*32;
            uint32_t a0 = h2ex2(h2pack(s[2*ks][0]   - mA, s[2*ks][1]   - mA));
            uint32_t a1 = h2ex2(h2pack(s[2*ks][2]   - mB, s[2*ks][3]   - mB));
            uint32_t a2 = h2ex2(h2pack(s[2*ks+1][0] - mA, s[2*ks+1][1] - mA));
            uint32_t a3 = h2ex2(h2pack(s[2*ks+1][2] - mB, s[2*ks+1][3] - mB));
            #pragma unroll
            for (int njp = 0; njp < 3; njp++) {
                uint32_t b0, b1, b2, b3;
                ldsm4(b0, b1, b2, b3, Vst_u + voff + njp*16*VTPADH*2 + kbb);
                mma16(o[2*njp],   a0, a1, a2, a3, b0, b1);
                mma16(o[2*njp+1], a0, a1, a2, a3, b2, b3);
            }
            uint32_t c0, c1;
            ldsm2(c0, c1, Vst_u + loff + kbb);
            mma16(l4, a0, a1, a2, a3, c0, c1);
        }
        if (++st == 3) st = 0;
    }

    /* epilogue: l lives in column 48 -> lane t==0 of each quad */
    float lA = __shfl_sync(0xffffffffu, l4[0], lane & 28);
    float lB = __shfl_sync(0xffffffffu, l4[2], lane & 28);
    float invA = 1.0f / lA, invB = 1.0f / lB;
    int rA = q0 + w*16 + g, rB = rA + 8;
    #pragma unroll
    for (int nj = 0; nj < 6; nj++) {
        int cb = nj*8 + 2*t;
        *(uint32_t*)(O + ((size_t)(b*NSEQ + rA))*BDIM + h*HD + cb) =
            h2pack(o[nj][0]*invA, o[nj][1]*invA);
        *(uint32_t*)(O + ((size_t)(b*NSEQ + rB))*BDIM + h*HD + cb) =
            h2pack(o[nj][2]*invB, o[nj][3]*invB);
    }
}

/* ------------------------------ launch ------------------------------ */
extern "C" void kernel_launch(void* const* d_in, const int* in_sizes, int n_in,
                              void* d_out, int out_size) {
    const float* x    = (const float*)d_in[0];
    const float* pos  = (const float*)d_in[1];
    const void*  mask = d_in[2];
    const float* Wq   = (const float*)d_in[3];
    const float* bq   = (const float*)d_in[4];
    const float* Wk   = (const float*)d_in[5];
    const float* bk   = (const float*)d_in[6];
    const float* Wv   = (const float*)d_in[7];
    const float* bv   = (const float*)d_in[8];
    const float* pw1  = (const float*)d_in[9];
    const float* pb1  = (const float*)d_in[10];
    const float* pw2  = (const float*)d_in[11];
    const float* pb2  = (const float*)d_in[12];
    const float* Wo   = (const float*)d_in[13];
    const float* bo   = (const float*)d_in[14];
    const float* mw1  = (const float*)d_in[15];
    const float* mb1  = (const float*)d_in[16];
    const float* mw2  = (const float*)d_in[17];
    const float* mb2  = (const float*)d_in[18];
    const float* g1   = (const float*)d_in[19];
    const float* be1  = (const float*)d_in[20];
    const float* g2   = (const float*)d_in[21];
    const float* be2  = (const float*)d_in[22];
    float* out = (float*)d_out;

    void *ph, *pq, *pk, *pv, *patt, *phid, *pwq, *pwo, *pm1, *pm2;
    void *ppe, *px1, *pm, *pmb, *pbq;
    cudaGetSymbolAddress(&ph,  g_h16);
    cudaGetSymbolAddress(&pq,  g_q16);
    cudaGetSymbolAddress(&pk,  g_k16);
    cudaGetSymbolAddress(&pv,  g_v16t);
    cudaGetSymbolAddress(&patt,g_att16);
    cudaGetSymbolAddress(&phid,g_hid16);
    cudaGetSymbolAddress(&pwq, g_wqkvT);
    cudaGetSymbolAddress(&pwo, g_woT);
    cudaGetSymbolAddress(&pm1, g_mw1T);
    cudaGetSymbolAddress(&pm2, g_mw2T);
    cudaGetSymbolAddress(&ppe, g_pe);
    cudaGetSymbolAddress(&px1, g_x1);
    cudaGetSymbolAddress(&pm,  g_mask);
    cudaGetSymbolAddress(&pmb, g_mb);
    cudaGetSymbolAddress(&pbq, g_bqkv);
    __half* h16   = (__half*)ph;
    __half* q16   = (__half*)pq;
    __half* k16   = (__half*)pk;
    __half* v16t  = (__half*)pv;
    __half* att16 = (__half*)patt;
    __half* hid16 = (__half*)phid;
    __half* wqkvT = (__half*)pwq;
    __half* woT   = (__half*)pwo;
    __half* mw1T  = (__half*)pm1;
    __half* mw2T  = (__half*)pm2;
    float* pe   = (float*)ppe;
    float* x1   = (float*)px1;
    int*   msk  = (int*)pm;
    float* mbf  = (float*)pmb;
    float* bqkv = (float*)pbq;

    cudaFuncSetAttribute(attn_tc,
                         cudaFuncAttributeMaxDynamicSharedMemorySize, ATT_SMEM);

    /* 1. fused prep: LN1 + pe + transposes + mask + bias pack */
    prep_kernel<<<3778, 256>>>(x, g1, be1, h16,
                               pos, pw1, pb1, pw2, pb2, pe,
                               Wq, Wk, Wv, Wo, mw1, mw2,
                               wqkvT, woT, mw1T, mw2T,
                               mask, msk, mbf,
                               bq, bk, bv, bqkv);
    /* 2. fused QKV projection (Q pre-scaled) */
    dim3 gqkv(MROWS/GBM, QKVN/GBN);
    gemm_tc<1><<<gqkv, 256>>>(h16, wqkvT, bqkv, BDIM, QKVN, pe, nullptr,
                              nullptr, q16, k16, v16t);
    /* 3. attention */
    dim3 ga(NSEQ/BQ, NB*HEADS);
    attn_tc<<<ga, 256, ATT_SMEM>>>(q16, k16, v16t, mbf, att16);
    /* 4. Wo + mask + residual -> x1 (f32) */
    dim3 gwo(MROWS/GBM, BDIM/GBN);
    gemm_tc<2><<<gwo, 256>>>(att16, woT, bo, BDIM, BDIM, x, msk,
                             x1, nullptr, nullptr, nullptr);
    /* 5. LN2 -> fp16 */
    ln_kernel<<<MROWS/8, 256>>>(x1, g2, be2, h16);
    /* 6. MLP1 + gelu -> fp16 */
    dim3 gm1(MROWS/GBM, MLPH/GBN);
    gemm_tc<3><<<gm1, 256>>>(h16, mw1T, mb1, BDIM, MLPH, nullptr, nullptr,
                             nullptr, hid16, nullptr, nullptr);
    /* 7. MLP2 + residual + mask -> out (f32) */
    gemm_tc<4><<<gwo, 256>>>(hid16, mw2T, mb2, MLPH, BDIM, x1, msk,
                             out, nullptr, nullptr, nullptr);
}

// round 14
// speedup vs baseline: 1.0140x; 1.0140x over previous
#include <cuda_runtime.h>
#include <cuda_fp16.h>
#include <math.h>
#include <stdint.h>

#define BDIM 384
#define HEADS 8
#define HD 48
#define NSEQ 2048
#define NB 4
#define MROWS (NB*NSEQ)      /* 8192 */
#define MLPH 1536
#define QKVN (3*BDIM)        /* 1152 */
#define SCALE2F (0.14433756729740643f * 1.4426950408889634f)  /* 48^-0.5 * log2e */

/* ------------ scratch (device globals; no allocation allowed) ------------ */
__device__ __half g_h16 [MROWS*BDIM];
__device__ __half g_q16 [MROWS*BDIM];
__device__ __half g_k16 [MROWS*BDIM];
__device__ __half g_v16t[MROWS*BDIM];          /* V^T: [bh][d][n] */
__device__ __half g_att16[MROWS*BDIM];
__device__ __half g_hid16[MROWS*MLPH];
__device__ __half g_wqkvT[QKVN*BDIM];
__device__ __half g_woT  [BDIM*BDIM];
__device__ __half g_mw1T [MLPH*BDIM];
__device__ __half g_mw2T [BDIM*MLPH];
__device__ float  g_pe[MROWS*HD];
__device__ float  g_x1[MROWS*BDIM];
__device__ int    g_mask[MROWS];
__device__ float  g_mb [MROWS];
__device__ float  g_bqkv[QKVN];

__device__ __forceinline__ float gelu_exact(float x) {
    return 0.5f * x * (1.0f + erff(x * 0.70710678118654752f));
}
__device__ __forceinline__ float ex2(float x) {
    float y; asm("ex2.approx.f32 %0, %1;" : "=f"(y) : "f"(x)); return y;
}
__device__ __forceinline__ uint32_t h2ex2(uint32_t x) {
    uint32_t y; asm("ex2.approx.f16x2 %0, %1;" : "=r"(y) : "r"(x)); return y;
}

/* m16n8k16 fp16 mma, fp32 accumulate. regs are packed half2. */
__device__ __forceinline__ void mma16(float* c,
                                      uint32_t a0, uint32_t a1, uint32_t a2, uint32_t a3,
                                      uint32_t b0, uint32_t b1) {
    asm volatile(
      "mma.sync.aligned.m16n8k16.row.col.f32.f16.f16.f32 "
      "{%0,%1,%2,%3},{%4,%5,%6,%7},{%8,%9},{%0,%1,%2,%3};"
      : "+f"(c[0]), "+f"(c[1]), "+f"(c[2]), "+f"(c[3])
      : "r"(a0), "r"(a1), "r"(a2), "r"(a3), "r"(b0), "r"(b1));
}

__device__ __forceinline__ void ldsm4(uint32_t& r0, uint32_t& r1,
                                      uint32_t& r2, uint32_t& r3, uint32_t a) {
    asm volatile("ldmatrix.sync.aligned.m8n8.x4.shared.b16 {%0,%1,%2,%3}, [%4];"
                 : "=r"(r0), "=r"(r1), "=r"(r2), "=r"(r3) : "r"(a));
}
__device__ __forceinline__ void ldsm2(uint32_t& r0, uint32_t& r1, uint32_t a) {
    asm volatile("ldmatrix.sync.aligned.m8n8.x2.shared.b16 {%0,%1}, [%2];"
                 : "=r"(r0), "=r"(r1) : "r"(a));
}
__device__ __forceinline__ uint32_t s2u(const void* p) {
    return (uint32_t)__cvta_generic_to_shared(p);
}
__device__ __forceinline__ void cpa16(void* dst, const void* src) {
    uint32_t d = s2u(dst);
    asm volatile("cp.async.ca.shared.global [%0], [%1], 16;" :: "r"(d), "l"(src));
}
__device__ __forceinline__ void cpa4(void* dst, const void* src) {
    uint32_t d = s2u(dst);
    asm volatile("cp.async.ca.shared.global [%0], [%1], 4;" :: "r"(d), "l"(src));
}
#define CP_COMMIT() asm volatile("cp.async.commit_group;")
template<int N> __device__ __forceinline__ void cp_wait() {
    asm volatile("cp.async.wait_group %0;" :: "n"(N));
}
__device__ __forceinline__ uint32_t h2pack(float a, float b) {
    __half2 h = __floats2half2_rn(a, b);
    return *(uint32_t*)&h;
}

/* ======================= fused prep kernel bodies ======================= */

__device__ __forceinline__ void ln_body(const float* __restrict__ X,
                                        const float* __restrict__ g,
                                        const float* __restrict__ be,
                                        __half* __restrict__ Y, int blk) {
    int tid = threadIdx.x, lane = tid & 31, w = tid >> 5;
    int row = blk*8 + w;
    const float* x = X + (size_t)row * BDIM;
    __half*      y = Y + (size_t)row * BDIM;
    float4 v[3];
    float s = 0.f, sq = 0.f;
    #pragma unroll
    for (int i = 0; i < 3; i++) {
        v[i] = *(const float4*)(x + lane*4 + i*128);
        s  += v[i].x + v[i].y + v[i].z + v[i].w;
        sq += v[i].x*v[i].x + v[i].y*v[i].y + v[i].z*v[i].z + v[i].w*v[i].w;
    }
    #pragma unroll
    for (int o = 16; o; o >>= 1) {
        s  += __shfl_xor_sync(0xffffffffu, s,  o);
        sq += __shfl_xor_sync(0xffffffffu, sq, o);
    }
    float mean = s * (1.0f / BDIM);
    float var  = sq * (1.0f / BDIM) - mean * mean;
    float rstd = rsqrtf(var + 1e-5f);
    #pragma unroll
    for (int i = 0; i < 3; i++) {
        int c = lane*4 + i*128;
        float4 gg = *(const float4*)(g + c);
        float4 bb = *(const float4*)(be + c);
        uint2 st;
        st.x = h2pack((v[i].x - mean)*rstd*gg.x + bb.x,
                      (v[i].y - mean)*rstd*gg.y + bb.y);
        st.y = h2pack((v[i].z - mean)*rstd*gg.z + bb.z,
                      (v[i].w - mean)*rstd*gg.w + bb.w);
        *(uint2*)(y + c) = st;
    }
}

__device__ __forceinline__ void pe_body(float* sh,
                                        const float* __restrict__ pos,
                                        const float* __restrict__ pw1,
                                        const float* __restrict__ pb1,
                                        const float* __restrict__ pw2,
                                        const float* __restrict__ pb2,
                                        float* __restrict__ pe, int blk) {
    float* w2s = sh;
    float* w1s = sh + 2304;
    float* b1s = sh + 2448;
    float* b2s = sh + 2496;
    int tid = threadIdx.x, lane = tid & 31, w = tid >> 5;
    for (int i = tid; i < HD*HD; i += 256) w2s[i] = pw2[i];
    if (tid < 3*HD) w1s[tid] = pw1[tid];
    else if (tid < 4*HD) b1s[tid - 3*HD] = pb1[tid - 3*HD];
    else if (tid < 5*HD) b2s[tid - 4*HD] = pb2[tid - 4*HD];
    __syncthreads();
    int row = blk*8 + w;
    float p0 = pos[row*3], p1 = pos[row*3+1], p2 = pos[row*3+2];
    float h0, h1 = 0.f;
    {
        int k = lane;
        h0 = gelu_exact(p0*w1s[k] + p1*w1s[HD+k] + p2*w1s[2*HD+k] + b1s[k]);
    }
    if (lane < 16) {
        int k = 32 + lane;
        h1 = gelu_exact(p0*w1s[k] + p1*w1s[HD+k] + p2*w1s[2*HD+k] + b1s[k]);
    }
    float acc0 = b2s[lane];
    float acc1 = (lane < 16) ? b2s[32 + lane] : 0.f;
    #pragma unroll 8
    for (int k = 0; k < HD; k++) {
        float hk = (k < 32) ? __shfl_sync(0xffffffffu, h0, k)
                            : __shfl_sync(0xffffffffu, h1, k - 32);
        acc0 += hk * w2s[k*HD + lane];
        if (lane < 16) acc1 += hk * w2s[k*HD + 32 + lane];
    }
    pe[(size_t)row*HD + lane] = acc0;
    if (lane < 16) pe[(size_t)row*HD + 32 + lane] = acc1;
}

__device__ __forceinline__ void transpose_body(float* sh,
                                               const float* __restrict__ Wq,
                                               const float* __restrict__ Wk,
                                               const float* __restrict__ Wv,
                                               const float* __restrict__ Wo,
                                               const float* __restrict__ mw1,
                                               const float* __restrict__ mw2,
                                               __half* __restrict__ wqkvT,
                                               __half* __restrict__ woT,
                                               __half* __restrict__ mw1T,
                                               __half* __restrict__ mw2T, int tIdx) {
    const float* W; __half* Wt; int K, N;
    if (tIdx < 432) {
        int seg = tIdx / 144;
        W  = (seg == 0) ? Wq : (seg == 1) ? Wk : Wv;
        Wt = wqkvT + (size_t)seg * BDIM * BDIM;
        K = BDIM; N = BDIM; tIdx -= seg * 144;
    } else if (tIdx < 576) { W = Wo;  Wt = woT;  K = BDIM; N = BDIM; tIdx -= 432; }
    else if   (tIdx < 1152) { W = mw1; Wt = mw1T; K = BDIM; N = MLPH; tIdx -= 576; }
    else                    { W = mw2; Wt = mw2T; K = MLPH; N = BDIM; tIdx -= 1152; }
    int nt = N / 32;
    int n0 = (tIdx % nt) * 32, k0 = (tIdx / nt) * 32;
    int tx = threadIdx.x & 31, ty = threadIdx.x >> 5;
    #pragma unroll
    for (int i = 0; i < 32; i += 8)
        sh[(ty+i)*33 + tx] = W[(size_t)(k0+ty+i)*N + n0+tx];
    __syncthreads();
    #pragma unroll
    for (int i = 0; i < 32; i += 8)
        Wt[(size_t)(n0+ty+i)*K + k0+tx] = __float2half_rn(sh[tx*33 + ty+i]);
}

__device__ __forceinline__ void mask_body(float* sh, const void* __restrict__ mptr,
                                          int n, int* __restrict__ out,
                                          float* __restrict__ fb) {
    int* ish = (int*)sh;
    const unsigned char* b = (const unsigned char*)mptr;
    if (threadIdx.x == 0) { ish[0] = 0; ish[1] = 0; }
    __syncthreads();
    int lf = 0, ln4 = 0;
    for (int i = threadIdx.x; i < n; i += 256) {
        unsigned char c = b[i];
        if (c == 0x3Fu && (i & 3) == 3) lf = 1;
        if (c != 0u   && (i & 3) != 0) ln4 = 1;
    }
    if (lf)  atomicOr(&ish[0], 1);
    if (ln4) atomicOr(&ish[1], 1);
    __syncthreads();
    int mode = ish[0] ? 2 : (ish[1] ? 0 : 1);
    for (int i = threadIdx.x; i < n; i += 256) {
        int v;
        if      (mode == 0) v = (b[i] != 0);
        else if (mode == 1) v = (((const int*)mptr)[i]   != 0);
        else                v = (((const float*)mptr)[i] != 0.0f);
        out[i] = v;
        fb[i]  = v ? 0.0f : -1e30f;
    }
}

__global__ __launch_bounds__(256)
void prep_kernel(const float* __restrict__ x,
                 const float* __restrict__ g1, const float* __restrict__ be1,
                 __half* __restrict__ h16,
                 const float* __restrict__ pos,
                 const float* __restrict__ pw1, const float* __restrict__ pb1,
                 const float* __restrict__ pw2, const float* __restrict__ pb2,
                 float* __restrict__ pe,
                 const float* __restrict__ Wq, const float* __restrict__ Wk,
                 const float* __restrict__ Wv, const float* __restrict__ Wo,
                 const float* __restrict__ mw1, const float* __restrict__ mw2,
                 __half* __restrict__ wqkvT, __half* __restrict__ woT,
                 __half* __restrict__ mw1T, __half* __restrict__ mw2T,
                 const void* __restrict__ mask, int* __restrict__ msk,
                 float* __restrict__ mbf,
                 const float* __restrict__ bq, const float* __restrict__ bk,
                 const float* __restrict__ bv, float* __restrict__ bqkv) {
    __shared__ float sh[2544];
    int bid = blockIdx.x;
    if (bid < 1024) {
        ln_body(x, g1, be1, h16, bid);
    } else if (bid < 2048) {
        pe_body(sh, pos, pw1, pb1, pw2, pb2, pe, bid - 1024);
    } else if (bid < 3776) {
        transpose_body(sh, Wq, Wk, Wv, Wo, mw1, mw2,
                       wqkvT, woT, mw1T, mw2T, bid - 2048);
    } else if (bid == 3776) {
        mask_body(sh, mask, MROWS, msk, mbf);
    } else {
        for (int i = threadIdx.x; i < QKVN; i += 256) {
            int sec = i / BDIM, c = i % BDIM;
            bqkv[i] = (sec == 0) ? bq[c] : (sec == 1) ? bk[c] : bv[c];
        }
    }
}

__global__ __launch_bounds__(256)
void ln_kernel(const float* __restrict__ X,
               const float* __restrict__ g,
               const float* __restrict__ be,
               __half* __restrict__ Y) {
    ln_body(X, g, be, Y, blockIdx.x);
}

/* ------------ fp16 GEMM: 128x128x32, 3-stage cp.async, 1 barrier/iter ----
   (R11 configuration — best measured)                                      */
#define GBM 128
#define GBN 128
#define GBK 32
#define APADH 40
#define BPADH 40
#define AST (GBM*APADH)
#define BST (GBN*BPADH)
#define GEMM_SMEM (3*(AST+BST)*2)     /* 61440 B */

template<int EPI>
__global__ __launch_bounds__(256, 2)
void gemm_tc(const __half* __restrict__ A, const __half* __restrict__ Bt,
             const float* __restrict__ bias,
             int K, int Nc,
             const float* __restrict__ extra, const int* __restrict__ mask,
             float* __restrict__ Cf, __half* __restrict__ Ch,
             __half* __restrict__ Ck, __half* __restrict__ Cv) {
    extern __shared__ __half gsm[];
    __half* As = gsm;
    __half* Bs = gsm + 3*AST;
    int tid = threadIdx.x, lane = tid & 31, w = tid >> 5;
    int g = lane >> 2, t = lane & 3;
    int wm = w >> 1, wn = w & 1;
    int bm = blockIdx.x * GBM, bn = blockIdx.y * GBN;
    int mlow = (lane >> 3) & 1, mhigh = lane >> 4, rr = lane & 7;

    float acc[2][8][4];
    #pragma unroll
    for (int mi = 0; mi < 2; mi++)
        #pragma unroll
        for (int nj = 0; nj < 8; nj++)
            #pragma unroll
            for (int r = 0; r < 4; r++) acc[mi][nj][r] = 0.f;

    int a_r = tid >> 2, a_c = (tid & 3) * 8;
    int b_r = tid >> 2, b_c = (tid & 3) * 8;

    uint32_t As_u = s2u(As);
    uint32_t Bs_u = s2u(Bs);
    uint32_t aoff0 = ((wm*32 + mlow*8 + rr)*APADH + mhigh*8)*2;
    uint32_t aoff1 = aoff0 + 16*APADH*2;
    uint32_t boffb = ((wn*64 + mhigh*8 + rr)*BPADH + mlow*8)*2;

    int ntiles = K / GBK;
    #pragma unroll
    for (int p = 0; p < 2; p++) {
        int k0 = p * GBK;
        cpa16(&As[p*AST + a_r*APADH + a_c], A + (size_t)(bm + a_r)*K + k0 + a_c);
        cpa16(&As[p*AST + (a_r+64)*APADH + a_c], A + (size_t)(bm + a_r + 64)*K + k0 + a_c);
        cpa16(&Bs[p*BST + b_r*BPADH + b_c], Bt + (size_t)(bn + b_r)*K + k0 + b_c);
        cpa16(&Bs[p*BST + (b_r+64)*BPADH + b_c], Bt + (size_t)(bn + b_r + 64)*K + k0 + b_c);
        CP_COMMIT();
    }

    int st = 0;
    for (int kt = 0; kt < ntiles; kt++) {
        cp_wait<1>();
        __syncthreads();
        if (kt + 2 < ntiles) {
            int k0 = (kt + 2) * GBK;
            int sn = st + 2; if (sn >= 3) sn -= 3;
            cpa16(&As[sn*AST + a_r*APADH + a_c], A + (size_t)(bm + a_r)*K + k0 + a_c);
            cpa16(&As[sn*AST + (a_r+64)*APADH + a_c], A + (size_t)(bm + a_r + 64)*K + k0 + a_c);
            cpa16(&Bs[sn*BST + b_r*BPADH + b_c], Bt + (size_t)(bn + b_r)*K + k0 + b_c);
            cpa16(&Bs[sn*BST + (b_r+64)*BPADH + b_c], Bt + (size_t)(bn + b_r + 64)*K + k0 + b_c);
        }
        CP_COMMIT();

        uint32_t asb = As_u + st*(AST*2);
        uint32_t bsb = Bs_u + st*(BST*2);
        #pragma unroll
        for (int ks = 0; ks < 2; ks++) {
            uint32_t kbb = ks*32;
            uint32_t af0[4], af1[4];
            ldsm4(af0[0], af0[1], af0[2], af0[3], asb + aoff0 + kbb);
            ldsm4(af1[0], af1[1], af1[2], af1[3], asb + aoff1 + kbb);
            #pragma unroll
            for (int njp = 0; njp < 4; njp++) {
                uint32_t b0, b1, b2, b3;
                ldsm4(b0, b1, b2, b3, bsb + boffb + njp*16*BPADH*2 + kbb);
                mma16(acc[0][2*njp],   af0[0], af0[1], af0[2], af0[3], b0, b1);
                mma16(acc[0][2*njp+1], af0[0], af0[1], af0[2], af0[3], b2, b3);
                mma16(acc[1][2*njp],   af1[0], af1[1], af1[2], af1[3], b0, b1);
                mma16(acc[1][2*njp+1], af1[0], af1[1], af1[2], af1[3], b2, b3);
            }
        }
        if (++st == 3) st = 0;
    }

    #pragma unroll
    for (int mi = 0; mi < 2; mi++) {
        #pragma unroll
        for (int half = 0; half < 2; half++) {
            int row = bm + wm*32 + mi*16 + g + half*8;
            #pragma unroll
            for (int nj = 0; nj < 8; nj++) {
                int col = bn + wn*64 + nj*8 + 2*t;
                float v0 = acc[mi][nj][half*2+0] + bias[col];
                float v1 = acc[mi][nj][half*2+1] + bias[col+1];
                if (EPI == 1) {
                    int sec = col / BDIM;
                    int c2  = col - sec*BDIM;
                    int d = c2 % HD, hh = c2 / HD;
                    int bb = row >> 11, n = row & (NSEQ-1);
                    if (sec == 2) {
                        __half* p = Cv + ((size_t)((bb*HEADS + hh)*HD + d))*NSEQ + n;
                        p[0]    = __float2half_rn(v0);
                        p[NSEQ] = __float2half_rn(v1);
                    } else if (sec == 1) {
                        v0 += extra[(size_t)row*HD + d];
                        v1 += extra[(size_t)row*HD + d + 1];
                        __half* p = Ck + (((size_t)(bb*HEADS + hh))*NSEQ + n)*HD + d;
                        *(uint32_t*)p = h2pack(v0, v1);
                    } else {
                        v0 *= SCALE2F; v1 *= SCALE2F;
                        __half* p = Ch + (((size_t)(bb*HEADS + hh))*NSEQ + n)*HD + d;
                        *(uint32_t*)p = h2pack(v0, v1);
                    }
                } else if (EPI == 2) {
                    float m = (float)mask[row];
                    v0 = v0*m + extra[(size_t)row*Nc + col];
                    v1 = v1*m + extra[(size_t)row*Nc + col + 1];
                    float* p = Cf + (size_t)row*Nc + col;
                    p[0] = v0; p[1] = v1;
                } else if (EPI == 3) {
                    *(uint32_t*)(Ch + (size_t)row*Nc + col) =
                        h2pack(gelu_exact(v0), gelu_exact(v1));
                } else {
                    float m = (float)mask[row];
                    v0 = (v0 + extra[(size_t)row*Nc + col])*m;
                    v1 = (v1 + extra[(size_t)row*Nc + col + 1])*m;
                    float* p = Cf + (size_t)row*Nc + col;
                    p[0] = v0; p[1] = v1;
                }
            }
        }
    }
}

/* ------- flash attention: 128-key stages, 2 sub-tiles per barrier window -- */
#define KPADH 56
#define VTPAD2 136
#define BQ 128
#define NT2 (NSEQ/128)                   /* 16 */
#define KST2 (128*KPADH)                 /* 7168 halves */
#define VST2 (56*VTPAD2)                 /* 7616 halves */
#define ATT_H_KS 0
#define ATT_H_VT (3*KST2)                /* 21504 */
#define ATT_H_QS (ATT_H_VT + 3*VST2)     /* 44352 */
#define ATT_H_END (ATT_H_QS + 128*KPADH) /* 51520 halves */
#define ATT_MB_OFF ATT_H_END
#define ATT_SMEM (ATT_H_END*2 + 3*128*4) /* 104576 B */

__global__ __launch_bounds__(256, 2)
void attn_tc(const __half* __restrict__ Q, const __half* __restrict__ Kb,
             const __half* __restrict__ Vt, const float* __restrict__ mb,
             __half* __restrict__ O) {
    extern __shared__ __half smh[];
    __half* Ks  = smh + ATT_H_KS;
    __half* Vts = smh + ATT_H_VT;
    __half* Qs  = smh + ATT_H_QS;
    float*  MBs = (float*)(smh + ATT_MB_OFF);

    int bh = blockIdx.y, b = bh >> 3, h = bh & 7;
    int q0 = blockIdx.x * BQ;
    int tid = threadIdx.x, lane = tid & 31, w = tid >> 5;
    int g = lane >> 2, t = lane & 3;
    int mlow = (lane >> 3) & 1, mhigh = lane >> 4, rr = lane & 7;
    const __half* qp = Q  + (size_t)bh * NSEQ * HD;
    const __half* kp = Kb + (size_t)bh * NSEQ * HD;
    const __half* vp = Vt + (size_t)bh * NSEQ * HD;   /* [d][n] */
    const float* mbp = mb + b * NSEQ;

    uint32_t Ks_u = s2u(Ks), Vt_u = s2u(Vts), Qs_u = s2u(Qs);
    uint32_t koff = ((mhigh*8 + rr)*KPADH + mlow*8)*2;
    uint32_t voff = ((mhigh*8 + rr)*VTPAD2 + mlow*8)*2;
    uint32_t loff = ((48 + rr)*VTPAD2 + mlow*8)*2;
    uint32_t qoff = Qs_u + ((w*16 + mlow*8 + rr)*KPADH + mhigh*8)*2;

    /* prologue: stages 0,1 (128 keys each) */
    #pragma unroll
    for (int p = 0; p < 2; p++) {
        int k0 = p * 128;
        #pragma unroll
        for (int i = 0; i < 3; i++) {        /* K: 128 rows x 6 chunks */
            int idx = tid + i*256;
            int r = idx / 6, c = (idx % 6) * 8;
            cpa16(Ks + p*KST2 + r*KPADH + c, kp + (size_t)(k0 + r)*HD + c);
        }
        #pragma unroll
        for (int i = 0; i < 3; i++) {        /* V: 48 rows x 16 chunks */
            int idx = tid + i*256;
            int rv = idx >> 4, cv = (idx & 15) * 8;
            cpa16(Vts + p*VST2 + rv*VTPAD2 + cv, vp + (size_t)rv*NSEQ + k0 + cv);
        }
        if (tid < 128) cpa4(MBs + p*128 + tid, mbp + k0 + tid);
        CP_COMMIT();
    }

    /* init ones/zeros rows 48..55 of V^T stages */
    {
        const __half one = __float2half(1.0f), zero = __float2half(0.0f);
        for (int idx = tid; idx < 3*8*128; idx += 256) {
            int stg = idx >> 10, rem = idx & 1023;
            int rw = 48 + (rem >> 7), cc = rem & 127;
            Vts[stg*VST2 + rw*VTPAD2 + cc] = (rw == 48) ? one : zero;
        }
    }

    /* stage Q ([128][56] halves), extract fragments */
    #pragma unroll
    for (int i = 0; i < 3; i++) {
        int idx = tid + i*256;
        int r = idx / 6, c = (idx % 6) * 8;
        *(uint4*)(Qs + r*KPADH + c) = *(const uint4*)(qp + (size_t)(q0 + r)*HD + c);
    }
    __syncthreads();
    uint32_t qf[3][4];
    #pragma unroll
    for (int ks = 0; ks < 3; ks++)
        ldsm4(qf[ks][0], qf[ks][1], qf[ks][2], qf[ks][3], qoff + ks*32);

    float o[6][4];
    #pragma unroll
    for (int nj = 0; nj < 6; nj++)
        #pragma unroll
        for (int r = 0; r < 4; r++) o[nj][r] = 0.f;
    float l4[4] = {0.f, 0.f, 0.f, 0.f};
    float mA = -INFINITY, mB = -INFINITY;

    int st = 0;
    for (int kt = 0; kt < NT2; kt++) {
        cp_wait<1>();
        __syncthreads();
        if (kt + 2 < NT2) {
            int k0 = (kt + 2) * 128;
            int sn = st + 2; if (sn >= 3) sn -= 3;
            #pragma unroll
            for (int i = 0; i < 3; i++) {
                int idx = tid + i*256;
                int r = idx / 6, c = (idx % 6) * 8;
                cpa16(Ks + sn*KST2 + r*KPADH + c, kp + (size_t)(k0 + r)*HD + c);
            }
            #pragma unroll
            for (int i = 0; i < 3; i++) {
                int idx = tid + i*256;
                int rv = idx >> 4, cv = (idx & 15) * 8;
                cpa16(Vts + sn*VST2 + rv*VTPAD2 + cv, vp + (size_t)rv*NSEQ + k0 + cv);
            }
            if (tid < 128) cpa4(MBs + sn*128 + tid, mbp + k0 + tid);
        }
        CP_COMMIT();

        /* two 64-key sub-tiles inside one barrier window */
        #pragma unroll
        for (int sub = 0; sub < 2; sub++) {
            uint32_t Kst_u = Ks_u + st*KST2*2 + sub*64*KPADH*2;
            uint32_t Vst_u = Vt_u + st*VST2*2 + sub*128;   /* +64 halves */
            const float* MBst = MBs + st*128 + sub*64;

            /* S = Q K^T : warp tile 16x64 (exp2-domain; Q pre-scaled) */
            float s[8][4];
            #pragma unroll
            for (int nj = 0; nj < 8; nj++)
                #pragma unroll
                for (int r = 0; r < 4; r++) s[nj][r] = 0.f;
            #pragma unroll
            for (int ks = 0; ks < 3; ks++) {
                uint32_t kbb = ks*32;
                #pragma unroll
                for (int njp = 0; njp < 4; njp++) {
                    uint32_t b0, b1, b2, b3;
                    ldsm4(b0, b1, b2, b3, Kst_u + koff + njp*16*KPADH*2 + kbb);
                    mma16(s[2*njp],   qf[ks][0], qf[ks][1], qf[ks][2], qf[ks][3], b0, b1);
                    mma16(s[2*njp+1], qf[ks][0], qf[ks][1], qf[ks][2], qf[ks][3], b2, b3);
                }
            }

            /* + mask bias, row max */
            float mxA = -INFINITY, mxB = -INFINITY;
            #pragma unroll
            for (int nj = 0; nj < 8; nj++) {
                float2 mbv = *(const float2*)(MBst + nj*8 + 2*t);
                s[nj][0] += mbv.x;
                s[nj][1] += mbv.y;
                s[nj][2] += mbv.x;
                s[nj][3] += mbv.y;
                mxA = fmaxf(mxA, fmaxf(s[nj][0], s[nj][1]));
                mxB = fmaxf(mxB, fmaxf(s[nj][2], s[nj][3]));
            }
            mxA = fmaxf(mxA, __shfl_xor_sync(0xffffffffu, mxA, 1));
            mxA = fmaxf(mxA, __shfl_xor_sync(0xffffffffu, mxA, 2));
            mxB = fmaxf(mxB, __shfl_xor_sync(0xffffffffu, mxB, 1));
            mxB = fmaxf(mxB, __shfl_xor_sync(0xffffffffu, mxB, 2));

            float mAn = fmaxf(mA, mxA), fA = ex2(mA - mAn);
            float mBn = fmaxf(mB, mxB), fB = ex2(mB - mBn);
            mA = mAn; mB = mBn;

            #pragma unroll
            for (int nj = 0; nj < 6; nj++) {
                o[nj][0] *= fA; o[nj][1] *= fA;
                o[nj][2] *= fB; o[nj][3] *= fB;
            }
            l4[0] *= fA; l4[2] *= fB;

            /* P = exp2(S-m) register-direct into PV mma */
            #pragma unroll
            for (int ks = 0; ks < 4; ks++) {
                uint32_t kbb = ks*32;
                uint32_t a0 = h2ex2(h2pack(s[2*ks][0]   - mA, s[2*ks][1]   - mA));
                uint32_t a1 = h2ex2(h2pack(s[2*ks][2]   - mB, s[2*ks][3]   - mB));
                uint32_t a2 = h2ex2(h2pack(s[2*ks+1][0] - mA, s[2*ks+1][1] - mA));
                uint32_t a3 = h2ex2(h2pack(s[2*ks+1][2] - mB, s[2*ks+1][3] - mB));
                #pragma unroll
                for (int njp = 0; njp < 3; njp++) {
                    uint32_t b0, b1, b2, b3;
                    ldsm4(b0, b1, b2, b3, Vst_u + voff + njp*16*VTPAD2*2 + kbb);
                    mma16(o[2*njp],   a0, a1, a2, a3, b0, b1);
                    mma16(o[2*njp+1], a0, a1, a2, a3, b2, b3);
                }
                uint32_t c0, c1;
                ldsm2(c0, c1, Vst_u + loff + kbb);
                mma16(l4, a0, a1, a2, a3, c0, c1);
            }
        }
        if (++st == 3) st = 0;
    }

    /* epilogue: l lives in column 48 -> lane t==0 of each quad */
    float lA = __shfl_sync(0xffffffffu, l4[0], lane & 28);
    float lB = __shfl_sync(0xffffffffu, l4[2], lane & 28);
    float invA = 1.0f / lA, invB = 1.0f / lB;
    int rA = q0 + w*16 + g, rB = rA + 8;
    #pragma unroll
    for (int nj = 0; nj < 6; nj++) {
        int cb = nj*8 + 2*t;
        *(uint32_t*)(O + ((size_t)(b*NSEQ + rA))*BDIM + h*HD + cb) =
            h2pack(o[nj][0]*invA, o[nj][1]*invA);
        *(uint32_t*)(O + ((size_t)(b*NSEQ + rB))*BDIM + h*HD + cb) =
            h2pack(o[nj][2]*invB, o[nj][3]*invB);
    }
}

/* ------------------------------ launch ------------------------------ */
extern "C" void kernel_launch(void* const* d_in, const int* in_sizes, int n_in,
                              void* d_out, int out_size) {
    const float* x    = (const float*)d_in[0];
    const float* pos  = (const float*)d_in[1];
    const void*  mask = d_in[2];
    const float* Wq   = (const float*)d_in[3];
    const float* bq   = (const float*)d_in[4];
    const float* Wk   = (const float*)d_in[5];
    const float* bk   = (const float*)d_in[6];
    const float* Wv   = (const float*)d_in[7];
    const float* bv   = (const float*)d_in[8];
    const float* pw1  = (const float*)d_in[9];
    const float* pb1  = (const float*)d_in[10];
    const float* pw2  = (const float*)d_in[11];
    const float* pb2  = (const float*)d_in[12];
    const float* Wo   = (const float*)d_in[13];
    const float* bo   = (const float*)d_in[14];
    const float* mw1  = (const float*)d_in[15];
    const float* mb1  = (const float*)d_in[16];
    const float* mw2  = (const float*)d_in[17];
    const float* mb2  = (const float*)d_in[18];
    const float* g1   = (const float*)d_in[19];
    const float* be1  = (const float*)d_in[20];
    const float* g2   = (const float*)d_in[21];
    const float* be2  = (const float*)d_in[22];
    float* out = (float*)d_out;

    void *ph, *pq, *pk, *pv, *patt, *phid, *pwq, *pwo, *pm1, *pm2;
    void *ppe, *px1, *pm, *pmb, *pbq;
    cudaGetSymbolAddress(&ph,  g_h16);
    cudaGetSymbolAddress(&pq,  g_q16);
    cudaGetSymbolAddress(&pk,  g_k16);
    cudaGetSymbolAddress(&pv,  g_v16t);
    cudaGetSymbolAddress(&patt,g_att16);
    cudaGetSymbolAddress(&phid,g_hid16);
    cudaGetSymbolAddress(&pwq, g_wqkvT);
    cudaGetSymbolAddress(&pwo, g_woT);
    cudaGetSymbolAddress(&pm1, g_mw1T);
    cudaGetSymbolAddress(&pm2, g_mw2T);
    cudaGetSymbolAddress(&ppe, g_pe);
    cudaGetSymbolAddress(&px1, g_x1);
    cudaGetSymbolAddress(&pm,  g_mask);
    cudaGetSymbolAddress(&pmb, g_mb);
    cudaGetSymbolAddress(&pbq, g_bqkv);
    __half* h16   = (__half*)ph;
    __half* q16   = (__half*)pq;
    __half* k16   = (__half*)pk;
    __half* v16t  = (__half*)pv;
    __half* att16 = (__half*)patt;
    __half* hid16 = (__half*)phid;
    __half* wqkvT = (__half*)pwq;
    __half* woT   = (__half*)pwo;
    __half* mw1T  = (__half*)pm1;
    __half* mw2T  = (__half*)pm2;
    float* pe   = (float*)ppe;
    float* x1   = (float*)px1;
    int*   msk  = (int*)pm;
    float* mbf  = (float*)pmb;
    float* bqkv = (float*)pbq;

    cudaFuncSetAttribute(attn_tc,
                         cudaFuncAttributeMaxDynamicSharedMemorySize, ATT_SMEM);
    cudaFuncSetAttribute(gemm_tc<1>,
                         cudaFuncAttributeMaxDynamicSharedMemorySize, GEMM_SMEM);
    cudaFuncSetAttribute(gemm_tc<2>,
                         cudaFuncAttributeMaxDynamicSharedMemorySize, GEMM_SMEM);
    cudaFuncSetAttribute(gemm_tc<3>,
                         cudaFuncAttributeMaxDynamicSharedMemorySize, GEMM_SMEM);
    cudaFuncSetAttribute(gemm_tc<4>,
                         cudaFuncAttributeMaxDynamicSharedMemorySize, GEMM_SMEM);

    /* 1. fused prep: LN1 + pe + transposes + mask + bias pack */
    prep_kernel<<<3778, 256>>>(x, g1, be1, h16,
                               pos, pw1, pb1, pw2, pb2, pe,
                               Wq, Wk, Wv, Wo, mw1, mw2,
                               wqkvT, woT, mw1T, mw2T,
                               mask, msk, mbf,
                               bq, bk, bv, bqkv);
    /* 2. fused QKV projection (Q pre-scaled) */
    dim3 gqkv(MROWS/GBM, QKVN/GBN);
    gemm_tc<1><<<gqkv, 256, GEMM_SMEM>>>(h16, wqkvT, bqkv, BDIM, QKVN, pe, nullptr,
                                         nullptr, q16, k16, v16t);
    /* 3. attention */
    dim3 ga(NSEQ/BQ, NB*HEADS);
    attn_tc<<<ga, 256, ATT_SMEM>>>(q16, k16, v16t, mbf, att16);
    /* 4. Wo + mask + residual -> x1 (f32) */
    dim3 gwo(MROWS/GBM, BDIM/GBN);
    gemm_tc<2><<<gwo, 256, GEMM_SMEM>>>(att16, woT, bo, BDIM, BDIM, x, msk,
                                        x1, nullptr, nullptr, nullptr);
    /* 5. LN2 -> fp16 */
    ln_kernel<<<MROWS/8, 256>>>(x1, g2, be2, h16);
    /* 6. MLP1 + gelu -> fp16 */
    dim3 gm1(MROWS/GBM, MLPH/GBN);
    gemm_tc<3><<<gm1, 256, GEMM_SMEM>>>(h16, mw1T, mb1, BDIM, MLPH, nullptr, nullptr,
                                        nullptr, hid16, nullptr, nullptr);
    /* 7. MLP2 + residual + mask -> out (f32) */
    gemm_tc<4><<<gwo, 256, GEMM_SMEM>>>(hid16, mw2T, mb2, MLPH, BDIM, x1, msk,
                                        out, nullptr, nullptr, nullptr);
}